// round 10
// baseline (speedup 1.0000x reference)
#include <cuda_runtime.h>
#include <cuda_fp16.h>
#include <cstdint>

// Shapes
#define S_ 256
#define BB 32
#define WMF 8192            // floats per (b,s) row, interleaved complex
#define PROW 4096           // floats per (b,s) row, planar
#define PLANE 33554432      // elems per plane (B*S*W*M)
#define NTHR 256
#define XP 72               // Xs row stride in halves (64 + 8 pad)

__device__ __align__(16) __half d_Wh[S_ * S_];   // diag(gain)*conn, fp16 [srow][k]
__device__ float2 d_tbl[S_ * 64];                // (decay*cos, decay*sin) per (s,w)
__device__ float2 d_scratch[PLANE];              // interleaved field buffer (268MB)

static __device__ __forceinline__ unsigned h2u(__half2 h) {
    return ((unsigned)__half_as_ushort(__high2half(h)) << 16) |
           (unsigned)__half_as_ushort(__low2half(h));
}
static __device__ __forceinline__ void ldsm4t(uint32_t* r, uint32_t a) {
    asm volatile("ldmatrix.sync.aligned.m8n8.x4.trans.shared.b16 {%0,%1,%2,%3}, [%4];"
                 : "=r"(r[0]), "=r"(r[1]), "=r"(r[2]), "=r"(r[3]) : "r"(a));
}
static __device__ __forceinline__ void mma16816(float* c, const uint32_t* a,
                                                uint32_t b0, uint32_t b1) {
    asm volatile(
        "mma.sync.aligned.m16n8k16.row.col.f32.f16.f16.f32 "
        "{%0,%1,%2,%3}, {%4,%5,%6,%7}, {%8,%9}, {%0,%1,%2,%3};"
        : "+f"(c[0]), "+f"(c[1]), "+f"(c[2]), "+f"(c[3])
        : "r"(a[0]), "r"(a[1]), "r"(a[2]), "r"(a[3]), "r"(b0), "r"(b1));
}

// ---------------------------------------------------------------------------
// Prep: dense fp16 W = diag(gain)*conn, fused phase/decay table.
// ---------------------------------------------------------------------------
__global__ void prep_kernel(const float* __restrict__ conn,
                            const float* __restrict__ gain,
                            const float* __restrict__ ww,
                            const float* __restrict__ disp) {
    int t = threadIdx.x;
    float g = gain[t];
    for (int j = 0; j < S_; j++)
        d_Wh[t * S_ + j] = __float2half(g * conn[t * S_ + j]);
    for (int i = t; i < S_ * 64; i += S_) {
        int w = i & 63;
        float phi = 0.1f * disp[w];
        float d = 0.95f * ww[i];
        d_tbl[i] = make_float2(d * cosf(phi), d * sinf(phi));
    }
}

// ---------------------------------------------------------------------------
// One fused step via mma.sync HMMA. CTA = (b, w, m-half): 64 scalar cols.
// Xs panel [256 k][64 scalar cols] fp16 staged once (36.9KB, 4 CTAs/SM).
// A-frags (W) loaded straight from gmem (L1/L2-hot) in mma layout -> no Ws
// smem, no per-chunk barriers. 8 warps = 4 m-stripes x 2 n-stripes, warp-tile
// m16 x n32. C-frag c0/c1 = (re,im) of one column -> shuffle-free epilogue.
// ---------------------------------------------------------------------------
template <bool PIN, bool POUT>
__global__ __launch_bounds__(NTHR, 4) void gemm_step(
    const float* __restrict__ inA,   // PIN: real plane; else interleaved base
    const float* __restrict__ inB,   // PIN: imag plane; else unused
    float* __restrict__ out,         // POUT: planar base; else interleaved base
    const float* __restrict__ gain,
    const float* __restrict__ bias) {
    extern __shared__ __half Xs[];   // [256][XP]

    int tid = threadIdx.x, warp = tid >> 5, lane = tid & 31;
    int bid = blockIdx.x;
    int b = bid >> 7, rem = bid & 127;
    int w = rem >> 1, half = rem & 1;
    size_t ibase = (size_t)b * ((size_t)S_ * WMF) + (size_t)w * 128;
    size_t pbase = (size_t)b * ((size_t)S_ * PROW) + (size_t)w * 64;

    // ---- stage X panel -> fp16 [k][scalar col within tile] ----
    if (PIN) {
        for (int idx = tid; idx < S_ * 8; idx += NTHR) {
            int k = idx >> 3, q = idx & 7;
            size_t pa = pbase + (size_t)k * PROW + half * 32 + 4 * q;
            float4 fr = *(const float4*)(inA + pa);
            float4 fi = *(const float4*)(inB + pa);
            uint4 pk = make_uint4(h2u(__floats2half2_rn(fr.x, fi.x)),
                                  h2u(__floats2half2_rn(fr.y, fi.y)),
                                  h2u(__floats2half2_rn(fr.z, fi.z)),
                                  h2u(__floats2half2_rn(fr.w, fi.w)));
            *(uint4*)(Xs + k * XP + 8 * q) = pk;
        }
    } else {
        for (int idx = tid; idx < S_ * 16; idx += NTHR) {
            int k = idx >> 4, q = idx & 15;
            float4 v = *(const float4*)(inA + ibase + (size_t)k * WMF +
                                        half * 64 + 4 * q);
            uint2 pk = make_uint2(h2u(__floats2half2_rn(v.x, v.y)),
                                  h2u(__floats2half2_rn(v.z, v.w)));
            *(uint2*)(Xs + k * XP + 4 * q) = pk;
        }
    }
    __syncthreads();   // the ONLY barrier

    uint32_t sX = (uint32_t)__cvta_generic_to_shared(Xs);
    int mstripe = (warp & 3) * 16;
    int n0w = (warp >> 2) * 32;                    // n-stripe within 64-col tile
    int lr = (lane & 7) + ((lane >> 3) & 1) * 8;   // ldmatrix row-within-16
    int lc = (lane >> 4) * 8;                      // ldmatrix col group 0/8
    int g8 = lane >> 2, t2 = (lane & 3) * 2;       // A-frag lane map
    uint32_t bBase = sX + (uint32_t)((lr * XP + n0w + lc) * 2);

    #pragma unroll 1
    for (int chunk = 0; chunk < 4; chunk++) {
        int srow0 = chunk * 64;
        const __half* W0 = d_Wh + (size_t)(srow0 + mstripe + g8) * S_;
        const __half* W1 = W0 + 8 * S_;

        float acc[4][4];
        #pragma unroll
        for (int i = 0; i < 4; i++)
            for (int j = 0; j < 4; j++) acc[i][j] = 0.f;

        #pragma unroll
        for (int ks = 0; ks < 16; ks++) {
            int k0 = ks * 16;
            uint32_t ra[4];
            ra[0] = *(const uint32_t*)(W0 + k0 + t2);       // A-frag direct LDG
            ra[1] = *(const uint32_t*)(W1 + k0 + t2);
            ra[2] = *(const uint32_t*)(W0 + k0 + t2 + 8);
            ra[3] = *(const uint32_t*)(W1 + k0 + t2 + 8);
            uint32_t rb[4], rb2[4];
            ldsm4t(rb, bBase + (uint32_t)(k0 * XP * 2));
            ldsm4t(rb2, bBase + (uint32_t)(k0 * XP * 2) + 32);
            mma16816(acc[0], ra, rb[0], rb[1]);
            mma16816(acc[1], ra, rb[2], rb[3]);
            mma16816(acc[2], ra, rb2[0], rb2[1]);
            mma16816(acc[3], ra, rb2[2], rb2[3]);
        }

        // ---- fused epilogue (no barrier; warps fully independent) ----
        #pragma unroll
        for (int nf = 0; nf < 4; nf++) {
            int scw = half * 64 + n0w + nf * 8 + 2 * (lane & 3);  // scalar re-col
            #pragma unroll
            for (int h = 0; h < 2; h++) {
                int srow = srow0 + mstripe + (lane >> 2) + h * 8;
                float cre = acc[nf][h * 2], cim = acc[nf][h * 2 + 1];
                float sre, sim;
                if (PIN) {
                    size_t pa = pbase + (size_t)srow * PROW + (scw >> 1);
                    sre = __ldg(inA + pa);
                    sim = __ldg(inB + pa);
                } else {
                    float2 s = __ldg((const float2*)(inA + ibase +
                                                     (size_t)srow * WMF + scw));
                    sre = s.x; sim = s.y;
                }
                float g = __ldg(gain + srow), bv = __ldg(bias + srow);
                float fre = fmaf(g, sre, cre + bv);   // bias -> real only
                float fim = fmaf(g, sim, cim);
                float inten = fmaf(fre, fre, fim * fim);
                float sc = __frcp_rn(fmaf(0.5f, inten, 1.0f));
                fre *= sc; fim *= sc;
                float2 dcs = d_tbl[(srow << 6) + w];
                float ore = fmaf(dcs.x, fre, -dcs.y * fim);
                float oim = fmaf(dcs.y, fre,  dcs.x * fim);
                if (POUT) {
                    size_t pa = pbase + (size_t)srow * PROW + (scw >> 1);
                    out[pa] = ore;
                    out[(size_t)PLANE + pa] = oim;
                } else {
                    *(float2*)(out + ibase + (size_t)srow * WMF + scw) =
                        make_float2(ore, oim);
                }
            }
        }
    }
}

// ---------------------------------------------------------------------------
// kernel_launch: prep + 4 HMMA steps, ping-pong scratch/d_out.
// ---------------------------------------------------------------------------
extern "C" void kernel_launch(void* const* d_in, const int* in_sizes, int n_in,
                              void* d_out, int out_size) {
    const float* fr   = (const float*)d_in[0];
    const float* fi   = (const float*)d_in[1];
    const float* conn = (const float*)d_in[2];
    const float* gain = (const float*)d_in[3];
    const float* bias = (const float*)d_in[4];
    const float* ww   = (const float*)d_in[5];
    const float* disp = (const float*)d_in[6];
    float* out = (float*)d_out;

    const int smem = S_ * XP * 2;   // 36,864 B
    cudaFuncSetAttribute(gemm_step<true,  false>,
                         cudaFuncAttributeMaxDynamicSharedMemorySize, smem);
    cudaFuncSetAttribute(gemm_step<false, false>,
                         cudaFuncAttributeMaxDynamicSharedMemorySize, smem);
    cudaFuncSetAttribute(gemm_step<false, true>,
                         cudaFuncAttributeMaxDynamicSharedMemorySize, smem);

    float* scratch = nullptr;
    cudaGetSymbolAddress((void**)&scratch, d_scratch);

    prep_kernel<<<1, 256>>>(conn, gain, ww, disp);

    dim3 grid(BB * 64 * 2);   // 4096 CTAs: (b, w, m-half)
    gemm_step<true,  false><<<grid, NTHR, smem>>>(fr, fi, scratch, gain, bias);
    gemm_step<false, false><<<grid, NTHR, smem>>>(scratch, nullptr, out, gain, bias);
    gemm_step<false, false><<<grid, NTHR, smem>>>(out, nullptr, scratch, gain, bias);
    gemm_step<false, true ><<<grid, NTHR, smem>>>(scratch, nullptr, out, gain, bias);
}

// round 11
// speedup vs baseline: 2.1868x; 2.1868x over previous
#include <cuda_runtime.h>
#include <cuda_fp16.h>
#include <cstdint>

#define S_ 256
#define BB 32
#define PROW 4096            // floats per (b,s) row, planar (W*M)
#define PLANE 33554432       // elems per plane (B*S*W*M)
#define NTHR 1024
#define XP 136               // Xs row stride in halves (128 + 8 pad)
#define KP 24                // Ws row stride in halves (16 + 8 pad)
#define WSBUF (S_ * KP)      // halves per Ws buffer

__device__ __align__(16) __half d_Wh[S_ * S_];   // diag(gain)*conn fp16 [srow][k]
__device__ float2 d_tbl[S_ * 64];                // (decay*cos, decay*sin) per (s,w)

static __device__ __forceinline__ unsigned h2u(__half2 h) {
    return ((unsigned)__half_as_ushort(__high2half(h)) << 16) |
           (unsigned)__half_as_ushort(__low2half(h));
}
static __device__ __forceinline__ void ldsm4(uint32_t* r, uint32_t a) {
    asm volatile("ldmatrix.sync.aligned.m8n8.x4.shared.b16 {%0,%1,%2,%3}, [%4];"
                 : "=r"(r[0]), "=r"(r[1]), "=r"(r[2]), "=r"(r[3]) : "r"(a));
}
static __device__ __forceinline__ void ldsm4t(uint32_t* r, uint32_t a) {
    asm volatile("ldmatrix.sync.aligned.m8n8.x4.trans.shared.b16 {%0,%1,%2,%3}, [%4];"
                 : "=r"(r[0]), "=r"(r[1]), "=r"(r[2]), "=r"(r[3]) : "r"(a));
}
static __device__ __forceinline__ void mma16816(float* c, const uint32_t* a,
                                                uint32_t b0, uint32_t b1) {
    asm volatile(
        "mma.sync.aligned.m16n8k16.row.col.f32.f16.f16.f32 "
        "{%0,%1,%2,%3}, {%4,%5,%6,%7}, {%8,%9}, {%0,%1,%2,%3};"
        : "+f"(c[0]), "+f"(c[1]), "+f"(c[2]), "+f"(c[3])
        : "r"(a[0]), "r"(a[1]), "r"(a[2]), "r"(a[3]), "r"(b0), "r"(b1));
}

// ---------------------------------------------------------------------------
__global__ void prep_kernel(const float* __restrict__ conn,
                            const float* __restrict__ gain,
                            const float* __restrict__ ww,
                            const float* __restrict__ disp) {
    int t = threadIdx.x;
    float g = gain[t];
    for (int j = 0; j < S_; j++)
        d_Wh[t * S_ + j] = __float2half(g * conn[t * S_ + j]);
    for (int i = t; i < S_ * 64; i += S_) {
        int w = i & 63;
        float phi = 0.1f * disp[w];
        float d = 0.95f * ww[i];
        d_tbl[i] = make_float2(d * cosf(phi), d * sinf(phi));
    }
}

// ---------------------------------------------------------------------------
// Fully fused 4-step kernel. CTA = (b, w). Xs fp16 panel persistent across
// steps; field state lives in the MMA accumulators (fp32, exact self term).
// 32 warps tile the 256x128 output as 8 m-stripes(x32) x 4 n-stripes(x32).
// ---------------------------------------------------------------------------
__global__ __launch_bounds__(NTHR, 1) void fused_kernel(
    const float* __restrict__ in0,   // real plane
    const float* __restrict__ in1,   // imag plane
    float* __restrict__ out,         // (2,B,S,W,M) planar
    const float* __restrict__ gain,
    const float* __restrict__ bias) {
    extern __shared__ __half sm[];
    __half* Xs = sm;                 // [256][XP]
    __half* Ws = sm + S_ * XP;       // [2][256][KP]

    int tid = threadIdx.x, warp = tid >> 5, lane = tid & 31;
    int b = blockIdx.x >> 6, w = blockIdx.x & 63;
    size_t pbase = (size_t)b * ((size_t)S_ * PROW) + (size_t)w * 64;

    // ---- stage Xs fp16 panel from planar input ----
    for (int idx = tid; idx < S_ * 16; idx += NTHR) {
        int k = idx >> 4, q = idx & 15;
        size_t pa = pbase + (size_t)k * PROW + 4 * q;
        float4 fr = *(const float4*)(in0 + pa);
        float4 fi = *(const float4*)(in1 + pa);
        uint4 pk = make_uint4(h2u(__floats2half2_rn(fr.x, fi.x)),
                              h2u(__floats2half2_rn(fr.y, fi.y)),
                              h2u(__floats2half2_rn(fr.z, fi.z)),
                              h2u(__floats2half2_rn(fr.w, fi.w)));
        *(uint4*)(Xs + k * XP + 8 * q) = pk;
    }

    int mstripe = (warp & 7) * 32;
    int nstripe = (warp >> 3) * 32;
    int lr = (lane & 7) + ((lane >> 3) & 1) * 8;
    int lc = (lane >> 4) * 8;
    int r4 = lane >> 2, c2 = 2 * (lane & 3);
    uint32_t sXa = (uint32_t)__cvta_generic_to_shared(Xs);
    uint32_t sWa = (uint32_t)__cvta_generic_to_shared(Ws);
    uint32_t bBase = sXa + (uint32_t)((lr * XP + nstripe + lc) * 2);

    // W staging role of this thread (one uint2 = 4 halves per k-block)
    int wm = tid >> 2, wk = (tid & 3) * 4;
    const __half* wsrc = d_Wh + wm * S_ + wk;
    __half* wdst0 = Ws + wm * KP + wk;

    // ---- init state: raw field into accumulators (exact fp32) ----
    float acc[2][4][4];
    #pragma unroll
    for (int mi = 0; mi < 2; mi++)
        #pragma unroll
        for (int h = 0; h < 2; h++) {
            int srow = mstripe + mi * 16 + h * 8 + r4;
            #pragma unroll
            for (int nj = 0; nj < 4; nj++) {
                int nsc = nstripe + nj * 8 + c2;
                size_t pa = pbase + (size_t)srow * PROW + (nsc >> 1);
                acc[mi][nj][2 * h]     = __ldg(in0 + pa);
                acc[mi][nj][2 * h + 1] = __ldg(in1 + pa);
            }
        }
    __syncthreads();   // Xs staged

    #pragma unroll 1
    for (int step = 0; step < 4; step++) {
        // ---- acc-init: acc = g*self + bias(real) ----
        #pragma unroll
        for (int mi = 0; mi < 2; mi++)
            #pragma unroll
            for (int h = 0; h < 2; h++) {
                int srow = mstripe + mi * 16 + h * 8 + r4;
                float g = __ldg(gain + srow), bv = __ldg(bias + srow);
                #pragma unroll
                for (int nj = 0; nj < 4; nj++) {
                    acc[mi][nj][2 * h]     = fmaf(g, acc[mi][nj][2 * h], bv);
                    acc[mi][nj][2 * h + 1] = g * acc[mi][nj][2 * h + 1];
                }
            }

        // ---- K loop: acc += (g*conn) @ X, double-buffered Ws ----
        *(uint2*)wdst0 = *(const uint2*)wsrc;            // k-block 0 -> buf 0
        uint2 rfut = *(const uint2*)(wsrc + 16);         // k-block 1
        __syncthreads();
        #pragma unroll
        for (int kb = 0; kb < 16; kb++) {
            uint32_t wsb = sWa + (uint32_t)(((kb & 1) * WSBUF) * 2);
            uint32_t rb[8];
            ldsm4t(rb,     bBase + (uint32_t)(kb * 16 * XP * 2));
            ldsm4t(rb + 4, bBase + (uint32_t)(kb * 16 * XP * 2) + 32);
            #pragma unroll
            for (int mi = 0; mi < 2; mi++) {
                uint32_t ra[4];
                ldsm4(ra, wsb + (uint32_t)(((mstripe + mi * 16 + lr) * KP + lc) * 2));
                mma16816(acc[mi][0], ra, rb[0], rb[1]);
                mma16816(acc[mi][1], ra, rb[2], rb[3]);
                mma16816(acc[mi][2], ra, rb[4], rb[5]);
                mma16816(acc[mi][3], ra, rb[6], rb[7]);
            }
            if (kb < 15) {
                *(uint2*)(Ws + ((kb + 1) & 1) * WSBUF + wm * KP + wk) = rfut;
                if (kb < 14) rfut = *(const uint2*)(wsrc + (kb + 2) * 16);
            }
            __syncthreads();
        }

        // ---- epilogue: saturate + rotate; state stays in acc ----
        #pragma unroll
        for (int mi = 0; mi < 2; mi++)
            #pragma unroll
            for (int h = 0; h < 2; h++) {
                int srow = mstripe + mi * 16 + h * 8 + r4;
                float2 dcs = __ldg(&d_tbl[(srow << 6) + w]);
                #pragma unroll
                for (int nj = 0; nj < 4; nj++) {
                    int nsc = nstripe + nj * 8 + c2;
                    float fre = acc[mi][nj][2 * h];
                    float fim = acc[mi][nj][2 * h + 1];
                    float inten = fmaf(fre, fre, fim * fim);
                    float sc = __frcp_rn(fmaf(0.5f, inten, 1.0f));
                    fre *= sc; fim *= sc;
                    float ore = fmaf(dcs.x, fre, -dcs.y * fim);
                    float oim = fmaf(dcs.y, fre,  dcs.x * fim);
                    acc[mi][nj][2 * h]     = ore;
                    acc[mi][nj][2 * h + 1] = oim;
                    if (step < 3) {
                        *(__half2*)(Xs + srow * XP + nsc) =
                            __floats2half2_rn(ore, oim);
                    } else {
                        size_t pa = pbase + (size_t)srow * PROW + (nsc >> 1);
                        out[pa] = ore;
                        out[(size_t)PLANE + pa] = oim;
                    }
                }
            }
        __syncthreads();   // Xs rewritten before next step's reads
    }
}

// ---------------------------------------------------------------------------
extern "C" void kernel_launch(void* const* d_in, const int* in_sizes, int n_in,
                              void* d_out, int out_size) {
    const float* fr   = (const float*)d_in[0];
    const float* fi   = (const float*)d_in[1];
    const float* conn = (const float*)d_in[2];
    const float* gain = (const float*)d_in[3];
    const float* bias = (const float*)d_in[4];
    const float* ww   = (const float*)d_in[5];
    const float* disp = (const float*)d_in[6];
    float* out = (float*)d_out;

    const int smem = (S_ * XP + 2 * WSBUF) * 2;   // 69,632 + 24,576 = 94,208 B
    cudaFuncSetAttribute(fused_kernel,
                         cudaFuncAttributeMaxDynamicSharedMemorySize, smem);

    prep_kernel<<<1, 256>>>(conn, gain, ww, disp);
    fused_kernel<<<BB * 64, NTHR, smem>>>(fr, fi, out, gain, bias);
}

// round 12
// speedup vs baseline: 2.5034x; 1.1448x over previous
#include <cuda_runtime.h>
#include <cuda_fp16.h>
#include <cstdint>

#define S_ 256
#define BB 32
#define PROW 4096            // floats per (b,s) row, planar (W*M)
#define PLANE 33554432       // elems per plane (B*S*W*M)
#define NTHR 1024
#define XP 136               // Xs row stride in halves (128 + 8 pad)
#define KWP 264              // Ws row stride in halves (256 + 8 pad)

__device__ __align__(16) __half d_Wh[S_ * S_];   // diag(gain)*conn fp16 [srow][k]
__device__ float2 d_tbl[S_ * 64];                // (decay*cos, decay*sin) per (s,w)

static __device__ __forceinline__ unsigned h2u(__half2 h) {
    return ((unsigned)__half_as_ushort(__high2half(h)) << 16) |
           (unsigned)__half_as_ushort(__low2half(h));
}
static __device__ __forceinline__ void ldsm4(uint32_t* r, uint32_t a) {
    asm volatile("ldmatrix.sync.aligned.m8n8.x4.shared.b16 {%0,%1,%2,%3}, [%4];"
                 : "=r"(r[0]), "=r"(r[1]), "=r"(r[2]), "=r"(r[3]) : "r"(a));
}
static __device__ __forceinline__ void ldsm4t(uint32_t* r, uint32_t a) {
    asm volatile("ldmatrix.sync.aligned.m8n8.x4.trans.shared.b16 {%0,%1,%2,%3}, [%4];"
                 : "=r"(r[0]), "=r"(r[1]), "=r"(r[2]), "=r"(r[3]) : "r"(a));
}
static __device__ __forceinline__ void mma16816(float* c, const uint32_t* a,
                                                uint32_t b0, uint32_t b1) {
    asm volatile(
        "mma.sync.aligned.m16n8k16.row.col.f32.f16.f16.f32 "
        "{%0,%1,%2,%3}, {%4,%5,%6,%7}, {%8,%9}, {%0,%1,%2,%3};"
        : "+f"(c[0]), "+f"(c[1]), "+f"(c[2]), "+f"(c[3])
        : "r"(a[0]), "r"(a[1]), "r"(a[2]), "r"(a[3]), "r"(b0), "r"(b1));
}

// ---------------------------------------------------------------------------
__global__ void prep_kernel(const float* __restrict__ conn,
                            const float* __restrict__ gain,
                            const float* __restrict__ ww,
                            const float* __restrict__ disp) {
    int t = threadIdx.x;
    float g = gain[t];
    for (int j = 0; j < S_; j++)
        d_Wh[t * S_ + j] = __float2half(g * conn[t * S_ + j]);
    for (int i = t; i < S_ * 64; i += S_) {
        int w = i & 63;
        float phi = 0.1f * disp[w];
        float d = 0.95f * ww[i];
        d_tbl[i] = make_float2(d * cosf(phi), d * sinf(phi));
    }
}

// ---------------------------------------------------------------------------
// Fully fused 4-step kernel. CTA = (b, w). Xs fp16 panel + FULL W matrix
// resident in SMEM (205KB); W staged once, so the K loop has ZERO barriers.
// Field state lives in fp32 MMA accumulators (exact self term).
// 32 warps tile the 256x128 output as 8 m-stripes(x32) x 4 n-stripes(x32).
// ---------------------------------------------------------------------------
__global__ __launch_bounds__(NTHR, 1) void fused_kernel(
    const float* __restrict__ in0,   // real plane
    const float* __restrict__ in1,   // imag plane
    float* __restrict__ out,         // (2,B,S,W,M) planar
    const float* __restrict__ gain,
    const float* __restrict__ bias) {
    extern __shared__ __half sm[];
    __half* Xs = sm;                 // [256][XP]
    __half* Ws = sm + S_ * XP;       // [256][KWP]

    int tid = threadIdx.x, warp = tid >> 5, lane = tid & 31;
    int b = blockIdx.x >> 6, w = blockIdx.x & 63;
    size_t pbase = (size_t)b * ((size_t)S_ * PROW) + (size_t)w * 64;

    // ---- stage full W matrix (once, reused by all 4 steps) ----
    for (int idx = tid; idx < S_ * 32; idx += NTHR) {
        int r = idx >> 5, q = idx & 31;
        *(uint4*)(Ws + r * KWP + 8 * q) = *(const uint4*)(d_Wh + r * S_ + 8 * q);
    }

    // ---- stage Xs fp16 panel from planar input ----
    for (int idx = tid; idx < S_ * 16; idx += NTHR) {
        int k = idx >> 4, q = idx & 15;
        size_t pa = pbase + (size_t)k * PROW + 4 * q;
        float4 fr = *(const float4*)(in0 + pa);
        float4 fi = *(const float4*)(in1 + pa);
        uint4 pk = make_uint4(h2u(__floats2half2_rn(fr.x, fi.x)),
                              h2u(__floats2half2_rn(fr.y, fi.y)),
                              h2u(__floats2half2_rn(fr.z, fi.z)),
                              h2u(__floats2half2_rn(fr.w, fi.w)));
        *(uint4*)(Xs + k * XP + 8 * q) = pk;
    }

    int mstripe = (warp & 7) * 32;
    int nstripe = (warp >> 3) * 32;
    int lr = (lane & 7) + ((lane >> 3) & 1) * 8;
    int lc = (lane >> 4) * 8;
    int r4 = lane >> 2, c2 = 2 * (lane & 3);
    uint32_t sXa = (uint32_t)__cvta_generic_to_shared(Xs);
    uint32_t sWa = (uint32_t)__cvta_generic_to_shared(Ws);
    uint32_t bBase = sXa + (uint32_t)((lr * XP + nstripe + lc) * 2);
    uint32_t a0Base = sWa + (uint32_t)(((mstripe + lr) * KWP + lc) * 2);
    uint32_t a1Base = a0Base + (uint32_t)(16 * KWP * 2);

    // ---- init state: raw field into accumulators (exact fp32) ----
    float acc[2][4][4];
    #pragma unroll
    for (int mi = 0; mi < 2; mi++)
        #pragma unroll
        for (int h = 0; h < 2; h++) {
            int srow = mstripe + mi * 16 + h * 8 + r4;
            #pragma unroll
            for (int nj = 0; nj < 4; nj++) {
                int nsc = nstripe + nj * 8 + c2;
                size_t pa = pbase + (size_t)srow * PROW + (nsc >> 1);
                acc[mi][nj][2 * h]     = __ldg(in0 + pa);
                acc[mi][nj][2 * h + 1] = __ldg(in1 + pa);
            }
        }
    __syncthreads();   // Ws + Xs staged

    #pragma unroll 1
    for (int step = 0; step < 4; step++) {
        // ---- acc-init: acc = g*self + bias(real) ----
        #pragma unroll
        for (int mi = 0; mi < 2; mi++)
            #pragma unroll
            for (int h = 0; h < 2; h++) {
                int srow = mstripe + mi * 16 + h * 8 + r4;
                float g = __ldg(gain + srow), bv = __ldg(bias + srow);
                #pragma unroll
                for (int nj = 0; nj < 4; nj++) {
                    acc[mi][nj][2 * h]     = fmaf(g, acc[mi][nj][2 * h], bv);
                    acc[mi][nj][2 * h + 1] = g * acc[mi][nj][2 * h + 1];
                }
            }

        // ---- K loop: acc += (g*conn) @ X ; NO barriers ----
        #pragma unroll
        for (int kb = 0; kb < 16; kb++) {
            uint32_t koff = (uint32_t)(kb * 16 * 2);
            uint32_t rb[8];
            ldsm4t(rb,     bBase + (uint32_t)(kb * 16 * XP * 2));
            ldsm4t(rb + 4, bBase + (uint32_t)(kb * 16 * XP * 2) + 32);
            uint32_t ra0[4], ra1[4];
            ldsm4(ra0, a0Base + koff);
            ldsm4(ra1, a1Base + koff);
            mma16816(acc[0][0], ra0, rb[0], rb[1]);
            mma16816(acc[0][1], ra0, rb[2], rb[3]);
            mma16816(acc[0][2], ra0, rb[4], rb[5]);
            mma16816(acc[0][3], ra0, rb[6], rb[7]);
            mma16816(acc[1][0], ra1, rb[0], rb[1]);
            mma16816(acc[1][1], ra1, rb[2], rb[3]);
            mma16816(acc[1][2], ra1, rb[4], rb[5]);
            mma16816(acc[1][3], ra1, rb[6], rb[7]);
        }
        __syncthreads();   // all Xs reads done before epilogue rewrites

        // ---- epilogue: saturate + rotate; state stays in acc ----
        #pragma unroll
        for (int mi = 0; mi < 2; mi++)
            #pragma unroll
            for (int h = 0; h < 2; h++) {
                int srow = mstripe + mi * 16 + h * 8 + r4;
                float2 dcs = __ldg(&d_tbl[(srow << 6) + w]);
                #pragma unroll
                for (int nj = 0; nj < 4; nj++) {
                    int nsc = nstripe + nj * 8 + c2;
                    float fre = acc[mi][nj][2 * h];
                    float fim = acc[mi][nj][2 * h + 1];
                    float inten = fmaf(fre, fre, fim * fim);
                    float sc = __frcp_rn(fmaf(0.5f, inten, 1.0f));
                    fre *= sc; fim *= sc;
                    float ore = fmaf(dcs.x, fre, -dcs.y * fim);
                    float oim = fmaf(dcs.y, fre,  dcs.x * fim);
                    acc[mi][nj][2 * h]     = ore;
                    acc[mi][nj][2 * h + 1] = oim;
                    if (step < 3) {
                        *(__half2*)(Xs + srow * XP + nsc) =
                            __floats2half2_rn(ore, oim);
                    } else {
                        size_t pa = pbase + (size_t)srow * PROW + (nsc >> 1);
                        out[pa] = ore;
                        out[(size_t)PLANE + pa] = oim;
                    }
                }
            }
        if (step < 3) __syncthreads();   // Xs rewritten before next step reads
    }
}

// ---------------------------------------------------------------------------
extern "C" void kernel_launch(void* const* d_in, const int* in_sizes, int n_in,
                              void* d_out, int out_size) {
    const float* fr   = (const float*)d_in[0];
    const float* fi   = (const float*)d_in[1];
    const float* conn = (const float*)d_in[2];
    const float* gain = (const float*)d_in[3];
    const float* bias = (const float*)d_in[4];
    const float* ww   = (const float*)d_in[5];
    const float* disp = (const float*)d_in[6];
    float* out = (float*)d_out;

    const int smem = (S_ * XP + S_ * KWP) * 2;   // 69,632 + 135,168 = 204,800 B
    cudaFuncSetAttribute(fused_kernel,
                         cudaFuncAttributeMaxDynamicSharedMemorySize, smem);

    prep_kernel<<<1, 256>>>(conn, gain, ww, disp);
    fused_kernel<<<BB * 64, NTHR, smem>>>(fr, fi, out, gain, bias);
}

// round 13
// speedup vs baseline: 2.5045x; 1.0005x over previous
#include <cuda_runtime.h>
#include <cuda_fp16.h>
#include <cstdint>

#define S_ 256
#define BB 32
#define PROW 4096            // floats per (b,s) row, planar (W*M)
#define PLANE 33554432       // elems per plane (B*S*W*M)
#define NTHR 1024
#define XP 136               // Xs row stride in halves (128 + 8 pad)
#define KWP 264              // Ws row stride in halves (256 + 8 pad)

__device__ __align__(16) __half d_Wh[S_ * S_];   // diag(gain)*conn fp16 [srow][k]
__device__ float2 d_tbl[S_ * 64];                // (decay*cos, decay*sin) per (s,w)

static __device__ __forceinline__ unsigned h2u(__half2 h) {
    return ((unsigned)__half_as_ushort(__high2half(h)) << 16) |
           (unsigned)__half_as_ushort(__low2half(h));
}
static __device__ __forceinline__ void ldsm4(uint32_t* r, uint32_t a) {
    asm volatile("ldmatrix.sync.aligned.m8n8.x4.shared.b16 {%0,%1,%2,%3}, [%4];"
                 : "=r"(r[0]), "=r"(r[1]), "=r"(r[2]), "=r"(r[3]) : "r"(a));
}
static __device__ __forceinline__ void ldsm4t(uint32_t* r, uint32_t a) {
    asm volatile("ldmatrix.sync.aligned.m8n8.x4.trans.shared.b16 {%0,%1,%2,%3}, [%4];"
                 : "=r"(r[0]), "=r"(r[1]), "=r"(r[2]), "=r"(r[3]) : "r"(a));
}
static __device__ __forceinline__ void mma16816(float* c, const uint32_t* a,
                                                uint32_t b0, uint32_t b1) {
    asm volatile(
        "mma.sync.aligned.m16n8k16.row.col.f32.f16.f16.f32 "
        "{%0,%1,%2,%3}, {%4,%5,%6,%7}, {%8,%9}, {%0,%1,%2,%3};"
        : "+f"(c[0]), "+f"(c[1]), "+f"(c[2]), "+f"(c[3])
        : "r"(a[0]), "r"(a[1]), "r"(a[2]), "r"(a[3]), "r"(b0), "r"(b1));
}

// ---------------------------------------------------------------------------
__global__ void prep_kernel(const float* __restrict__ conn,
                            const float* __restrict__ gain,
                            const float* __restrict__ ww,
                            const float* __restrict__ disp) {
    int t = threadIdx.x;
    float g = gain[t];
    for (int j = 0; j < S_; j++)
        d_Wh[t * S_ + j] = __float2half(g * conn[t * S_ + j]);
    for (int i = t; i < S_ * 64; i += S_) {
        int w = i & 63;
        float phi = 0.1f * disp[w];
        float d = 0.95f * ww[i];
        d_tbl[i] = make_float2(d * cosf(phi), d * sinf(phi));
    }
}

// ---------------------------------------------------------------------------
// Fully fused 4-step kernel. CTA = (b, w). Xs fp16 panel + FULL W matrix
// resident in SMEM; zero barriers in the K loop. K loop split into two
// n-halves with short-lived frag groups so ptxas can pipeline ldsm across
// k-blocks within the 64-reg budget.
// ---------------------------------------------------------------------------
__global__ __launch_bounds__(NTHR, 1) void fused_kernel(
    const float* __restrict__ in0,   // real plane
    const float* __restrict__ in1,   // imag plane
    float* __restrict__ out,         // (2,B,S,W,M) planar
    const float* __restrict__ gain,
    const float* __restrict__ bias) {
    extern __shared__ __half sm[];
    __half* Xs = sm;                 // [256][XP]
    __half* Ws = sm + S_ * XP;       // [256][KWP]

    int tid = threadIdx.x, warp = tid >> 5, lane = tid & 31;
    int b = blockIdx.x >> 6, w = blockIdx.x & 63;
    size_t pbase = (size_t)b * ((size_t)S_ * PROW) + (size_t)w * 64;

    // ---- stage full W matrix (once, reused by all 4 steps) ----
    for (int idx = tid; idx < S_ * 32; idx += NTHR) {
        int r = idx >> 5, q = idx & 31;
        *(uint4*)(Ws + r * KWP + 8 * q) = *(const uint4*)(d_Wh + r * S_ + 8 * q);
    }

    // ---- stage Xs fp16 panel from planar input ----
    for (int idx = tid; idx < S_ * 16; idx += NTHR) {
        int k = idx >> 4, q = idx & 15;
        size_t pa = pbase + (size_t)k * PROW + 4 * q;
        float4 fr = *(const float4*)(in0 + pa);
        float4 fi = *(const float4*)(in1 + pa);
        uint4 pk = make_uint4(h2u(__floats2half2_rn(fr.x, fi.x)),
                              h2u(__floats2half2_rn(fr.y, fi.y)),
                              h2u(__floats2half2_rn(fr.z, fi.z)),
                              h2u(__floats2half2_rn(fr.w, fi.w)));
        *(uint4*)(Xs + k * XP + 8 * q) = pk;
    }

    int mstripe = (warp & 7) * 32;
    int nstripe = (warp >> 3) * 32;
    int lr = (lane & 7) + ((lane >> 3) & 1) * 8;
    int lc = (lane >> 4) * 8;
    int r4 = lane >> 2, c2 = 2 * (lane & 3);
    uint32_t sXa = (uint32_t)__cvta_generic_to_shared(Xs);
    uint32_t sWa = (uint32_t)__cvta_generic_to_shared(Ws);
    uint32_t bBase = sXa + (uint32_t)((lr * XP + nstripe + lc) * 2);
    uint32_t a0Base = sWa + (uint32_t)(((mstripe + lr) * KWP + lc) * 2);
    uint32_t a1Base = a0Base + (uint32_t)(16 * KWP * 2);

    // ---- init state: raw field into accumulators (exact fp32) ----
    float acc[2][4][4];
    #pragma unroll
    for (int mi = 0; mi < 2; mi++)
        #pragma unroll
        for (int h = 0; h < 2; h++) {
            int srow = mstripe + mi * 16 + h * 8 + r4;
            #pragma unroll
            for (int nj = 0; nj < 4; nj++) {
                int nsc = nstripe + nj * 8 + c2;
                size_t pa = pbase + (size_t)srow * PROW + (nsc >> 1);
                acc[mi][nj][2 * h]     = __ldg(in0 + pa);
                acc[mi][nj][2 * h + 1] = __ldg(in1 + pa);
            }
        }
    __syncthreads();   // Ws + Xs staged

    #pragma unroll 1
    for (int step = 0; step < 4; step++) {
        // ---- acc-init: acc = g*self + bias(real) ----
        #pragma unroll
        for (int mi = 0; mi < 2; mi++)
            #pragma unroll
            for (int h = 0; h < 2; h++) {
                int srow = mstripe + mi * 16 + h * 8 + r4;
                float g = __ldg(gain + srow), bv = __ldg(bias + srow);
                #pragma unroll
                for (int nj = 0; nj < 4; nj++) {
                    acc[mi][nj][2 * h]     = fmaf(g, acc[mi][nj][2 * h], bv);
                    acc[mi][nj][2 * h + 1] = g * acc[mi][nj][2 * h + 1];
                }
            }

        // ---- K loop: acc += (g*conn) @ X ; no barriers; pipelined halves ----
        #pragma unroll
        for (int kb = 0; kb < 16; kb++) {
            uint32_t koff = (uint32_t)(kb * 16 * 2);
            uint32_t xoff = (uint32_t)(kb * 16 * XP * 2);
            uint32_t ra0[4], ra1[4];
            ldsm4(ra0, a0Base + koff);
            ldsm4(ra1, a1Base + koff);
            {   // n-half A (cols 0-15) — loads for half B issued below mma A
                uint32_t rbA[4];
                ldsm4t(rbA, bBase + xoff);
                uint32_t rbB[4];
                ldsm4t(rbB, bBase + xoff + 32);
                mma16816(acc[0][0], ra0, rbA[0], rbA[1]);
                mma16816(acc[0][1], ra0, rbA[2], rbA[3]);
                mma16816(acc[1][0], ra1, rbA[0], rbA[1]);
                mma16816(acc[1][1], ra1, rbA[2], rbA[3]);
                mma16816(acc[0][2], ra0, rbB[0], rbB[1]);
                mma16816(acc[0][3], ra0, rbB[2], rbB[3]);
                mma16816(acc[1][2], ra1, rbB[0], rbB[1]);
                mma16816(acc[1][3], ra1, rbB[2], rbB[3]);
            }
        }
        __syncthreads();   // all Xs reads done before epilogue rewrites

        // ---- epilogue: saturate + rotate; state stays in acc ----
        #pragma unroll
        for (int mi = 0; mi < 2; mi++)
            #pragma unroll
            for (int h = 0; h < 2; h++) {
                int srow = mstripe + mi * 16 + h * 8 + r4;
                float2 dcs = __ldg(&d_tbl[(srow << 6) + w]);
                #pragma unroll
                for (int nj = 0; nj < 4; nj++) {
                    int nsc = nstripe + nj * 8 + c2;
                    float fre = acc[mi][nj][2 * h];
                    float fim = acc[mi][nj][2 * h + 1];
                    float inten = fmaf(fre, fre, fim * fim);
                    float sc = __frcp_rn(fmaf(0.5f, inten, 1.0f));
                    fre *= sc; fim *= sc;
                    float ore = fmaf(dcs.x, fre, -dcs.y * fim);
                    float oim = fmaf(dcs.y, fre,  dcs.x * fim);
                    acc[mi][nj][2 * h]     = ore;
                    acc[mi][nj][2 * h + 1] = oim;
                    if (step < 3) {
                        *(__half2*)(Xs + srow * XP + nsc) =
                            __floats2half2_rn(ore, oim);
                    } else {
                        size_t pa = pbase + (size_t)srow * PROW + (nsc >> 1);
                        out[pa] = ore;
                        out[(size_t)PLANE + pa] = oim;
                    }
                }
            }
        if (step < 3) __syncthreads();   // Xs rewritten before next step reads
    }
}

// ---------------------------------------------------------------------------
extern "C" void kernel_launch(void* const* d_in, const int* in_sizes, int n_in,
                              void* d_out, int out_size) {
    const float* fr   = (const float*)d_in[0];
    const float* fi   = (const float*)d_in[1];
    const float* conn = (const float*)d_in[2];
    const float* gain = (const float*)d_in[3];
    const float* bias = (const float*)d_in[4];
    const float* ww   = (const float*)d_in[5];
    const float* disp = (const float*)d_in[6];
    float* out = (float*)d_out;

    const int smem = (S_ * XP + S_ * KWP) * 2;   // 204,800 B
    cudaFuncSetAttribute(fused_kernel,
                         cudaFuncAttributeMaxDynamicSharedMemorySize, smem);

    prep_kernel<<<1, 256>>>(conn, gain, ww, disp);
    fused_kernel<<<BB * 64, NTHR, smem>>>(fr, fi, out, gain, bias);
}